// round 13
// baseline (speedup 1.0000x reference)
#include <cuda_runtime.h>
#include <cuda_bf16.h>
#include <cstdint>
#include <cstddef>
#include <math.h>

#define EMB   256
#define NB    512
#define ENT_N 100000
#define REL_N 2000
#define SPLITS_E 37
#define SPLITS_R 8
#define QP16  264                 // bf16 pitch for 256-wide tiles (+8 pad, 16B aligned)
#define PPITCH 72                 // P tile pitch (64+8)
#define FL_SMEM ((3*64*QP16 + 64*PPITCH)*2)   // Q + 2 E buffers + P = 110592 B

// ---------------- scratch (device globals; no allocation) ----------------
__device__ __align__(16) __nv_bfloat16 g_qe16[NB*EMB];
__device__ __align__(16) __nv_bfloat16 g_ql16[NB*EMB];
__device__ __align__(16) __nv_bfloat16 g_qr16[NB*EMB];
__device__ __align__(16) __nv_bfloat16 g_ent16[(ENT_N+64)*EMB];
__device__ __align__(16) __nv_bfloat16 g_rel16[(REL_N+64)*EMB];
__device__ __align__(16) __nv_bfloat16 g_q16[NB*768];      // bf16 q_cat
__device__ __align__(16) __nv_bfloat16 g_wl16[256*256];
__device__ __align__(16) __nv_bfloat16 g_wr16[256*256];
__device__ __align__(16) __nv_bfloat16 g_we16[256*768];

__device__ float g_pacc0[SPLITS_E*NB*EMB];
__device__ float g_pl0[SPLITS_E*NB];
__device__ float g_pacc1[SPLITS_R*NB*EMB];
__device__ float g_pl1[SPLITS_R*NB];
__device__ float g_pacc2[SPLITS_R*NB*EMB];
__device__ float g_pl2[SPLITS_R*NB];

// ---------------- small PTX helpers ----------------
__device__ __forceinline__ unsigned smem_u32(const void* p){
    return (unsigned)__cvta_generic_to_shared(p);
}
__device__ __forceinline__ void ldsm4(unsigned* r, unsigned addr){
    asm volatile("ldmatrix.sync.aligned.m8n8.x4.shared.b16 {%0,%1,%2,%3}, [%4];"
      : "=r"(r[0]),"=r"(r[1]),"=r"(r[2]),"=r"(r[3]) : "r"(addr));
}
__device__ __forceinline__ void ldsm4t(unsigned* r, unsigned addr){
    asm volatile("ldmatrix.sync.aligned.m8n8.x4.trans.shared.b16 {%0,%1,%2,%3}, [%4];"
      : "=r"(r[0]),"=r"(r[1]),"=r"(r[2]),"=r"(r[3]) : "r"(addr));
}
__device__ __forceinline__ void mma16816(float* d, const unsigned* a, unsigned b0, unsigned b1){
    asm volatile("mma.sync.aligned.m16n8k16.row.col.f32.bf16.bf16.f32 "
      "{%0,%1,%2,%3}, {%4,%5,%6,%7}, {%8,%9}, {%0,%1,%2,%3};"
      : "+f"(d[0]),"+f"(d[1]),"+f"(d[2]),"+f"(d[3])
      : "r"(a[0]),"r"(a[1]),"r"(a[2]),"r"(a[3]), "r"(b0),"r"(b1));
}
__device__ __forceinline__ void cpasync16(unsigned dst, const void* src){
    asm volatile("cp.async.cg.shared.global [%0], [%1], 16;" :: "r"(dst), "l"(src));
}
#define CP_COMMIT() asm volatile("cp.async.commit_group;" ::: "memory")
#define CP_WAIT_1() asm volatile("cp.async.wait_group 1;" ::: "memory")
#define CP_WAIT_0() asm volatile("cp.async.wait_group 0;" ::: "memory")

__device__ __forceinline__ unsigned packbf(float lo, float hi){
    __nv_bfloat162 h = __floats2bfloat162_rn(lo, hi);
    return *reinterpret_cast<unsigned*>(&h);
}

// ---------------- merged fp32 -> bf16 conversions (8 elems/thread) ----------------
// segments: ent(pad) | rel(pad) | query | Wl | Wr | We   (all boundaries 8-divisible)
#define S0E 25616384LL
#define S1E 26144768LL
#define S2E 26537984LL
#define S3E 26603520LL
#define S4E 26669056LL
#define S5E 26865664LL
__global__ __launch_bounds__(256) void conv_all(
    const float* __restrict__ ent, const float* __restrict__ rel,
    const float* __restrict__ query,
    const float* __restrict__ Wl, const float* __restrict__ Wr,
    const float* __restrict__ We)
{
    long long i = ((long long)blockIdx.x*256 + threadIdx.x)*8;
    if (i >= S5E) return;
    const float* src; __nv_bfloat16* dst; long long off, n;
    if (i < S0E)      { src=ent;   dst=g_ent16; off=i;       n=25600000LL; }
    else if (i < S1E) { src=rel;   dst=g_rel16; off=i-S0E;   n=512000LL; }
    else if (i < S2E) { src=query; dst=g_q16;   off=i-S1E;   n=393216LL; }
    else if (i < S3E) { src=Wl;    dst=g_wl16;  off=i-S2E;   n=65536LL; }
    else if (i < S4E) { src=Wr;    dst=g_wr16;  off=i-S3E;   n=65536LL; }
    else              { src=We;    dst=g_we16;  off=i-S4E;   n=196608LL; }
    float4 v0 = make_float4(0.f,0.f,0.f,0.f), v1 = v0;
    if (off < n) {
        v0 = *(const float4*)(src+off);
        v1 = *(const float4*)(src+off+4);
    }
    uint4 o;
    o.x = packbf(v0.x, v0.y);
    o.y = packbf(v0.z, v0.w);
    o.z = packbf(v1.x, v1.y);
    o.w = packbf(v1.z, v1.w);
    *(uint4*)(dst+off) = o;
}

// ---------------- projections via bf16 mma: q_ent / left_rel / right_rel ----------
// grid (8 bt, 12 nc): nc>>2 = mat (0=L,1=R,2=E), (nc&3)*64 = output col chunk.
#define PJP 72   // smem pitch (64+8)
__global__ __launch_bounds__(128) void proj16(
    const float* __restrict__ bl, const float* __restrict__ br,
    const float* __restrict__ be)
{
    __shared__ __nv_bfloat16 ts[4][64*PJP];   // q0,q1,w0,w1

    const int bt = blockIdx.x, nc = blockIdx.y;
    const int mat = nc >> 2, ncol = (nc & 3) * 64;
    const __nv_bfloat16 *W, *Qb;
    const float* bias;
    __nv_bfloat16* dst;
    int K;
    if (mat == 0)      { W = g_wl16 + ncol*256; bias = bl; dst = g_ql16; K = 256; Qb = g_q16 + 256; }
    else if (mat == 1) { W = g_wr16 + ncol*256; bias = br; dst = g_qr16; K = 256; Qb = g_q16 + 256; }
    else               { W = g_we16 + ncol*768; bias = be; dst = g_qe16; K = 768; Qb = g_q16; }
    const int nk = K >> 6;

    const int tid = threadIdx.x, warp = tid>>5, lane = tid&31;
    const unsigned qs[2] = { smem_u32(ts[0]), smem_u32(ts[1]) };
    const unsigned ws[2] = { smem_u32(ts[2]), smem_u32(ts[3]) };

    const int lr = tid >> 3, lc8 = (tid & 7) * 8;
    {
#pragma unroll
        for (int j = 0; j < 4; j++) {
            int r = lr + j*16;
            cpasync16(qs[0] + (r*PJP + lc8)*2, Qb + (bt*64 + r)*768 + lc8);
            cpasync16(ws[0] + (r*PJP + lc8)*2, W + r*K + lc8);
        }
        CP_COMMIT();
    }

    const int am = lane>>3;
    const unsigned aOff = (((warp<<4) + (lane&7) + ((am&1)<<3))*PJP + ((am>>1)<<3))*2;
    const unsigned bOff = ((lane&7)*PJP + ((lane>>3)&1)*8 + ((lane>>4)*8*PJP))*2;

    float s[8][4];
#pragma unroll
    for (int i = 0; i < 8; i++) { s[i][0]=0.f; s[i][1]=0.f; s[i][2]=0.f; s[i][3]=0.f; }

    for (int kc = 0; kc < nk; kc++) {
        if (kc + 1 < nk) {
            const int koff = (kc+1)*64;
            const unsigned qd = qs[(kc+1)&1], wd = ws[(kc+1)&1];
#pragma unroll
            for (int j = 0; j < 4; j++) {
                int r = lr + j*16;
                cpasync16(qd + (r*PJP + lc8)*2, Qb + (bt*64 + r)*768 + koff + lc8);
                cpasync16(wd + (r*PJP + lc8)*2, W + r*K + koff + lc8);
            }
            CP_COMMIT();
            CP_WAIT_1();
        } else {
            CP_WAIT_0();
        }
        __syncthreads();
        const unsigned qb = qs[kc&1], wb = ws[kc&1];
#pragma unroll
        for (int kt = 0; kt < 4; kt++) {
            unsigned a[4]; ldsm4(a, qb + aOff + kt*32);
#pragma unroll
            for (int nt = 0; nt < 8; nt += 2) {
                unsigned r[4];
                ldsm4(r, wb + bOff + (nt*8*PJP)*2 + kt*32);
                mma16816(s[nt],   a, r[0], r[1]);
                mma16816(s[nt+1], a, r[2], r[3]);
            }
        }
        __syncthreads();
    }

    const int rowA = bt*64 + warp*16 + (lane>>2);
    const int rowB = rowA + 8;
#pragma unroll
    for (int nt = 0; nt < 8; nt++) {
        int col = ncol + nt*8 + (lane&3)*2;
        float b0 = bias[col], b1 = bias[col+1];
        *(__nv_bfloat162*)(dst + rowA*EMB + col) = __floats2bfloat162_rn(s[nt][0]+b0, s[nt][1]+b1);
        *(__nv_bfloat162*)(dst + rowB*EMB + col) = __floats2bfloat162_rn(s[nt][2]+b0, s[nt][3]+b1);
    }
}

// ---------------- bf16 tensor-core flash attend (merged ent+rel, split-K) -----------
// 424 blocks: [0,296) ent, [296,360) left rel, [360,424) right rel.  (M=64, 2 blk/SM)
// S row-split (warp=16 rows); PV column-split (warp=64 cols, all rows) via P in smem.
__global__ __launch_bounds__(128) void flash16(int dummy)
{
    int id = blockIdx.x;
    const __nv_bfloat16 *Q, *tbl;
    float *pacc, *pl;
    int N, splits;
    if (id < 296)      { Q = g_qe16; tbl = g_ent16; pacc = g_pacc0; pl = g_pl0; N = ENT_N; splits = SPLITS_E; }
    else if (id < 360) { id -= 296; Q = g_ql16; tbl = g_rel16; pacc = g_pacc1; pl = g_pl1; N = REL_N; splits = SPLITS_R; }
    else               { id -= 360; Q = g_qr16; tbl = g_rel16; pacc = g_pacc2; pl = g_pl2; N = REL_N; splits = SPLITS_R; }
    const int bt = id & 7, sp = id >> 3;

    extern __shared__ __nv_bfloat16 sh[];
    __nv_bfloat16* q_s = sh;                 // 64 x QP16
    __nv_bfloat16* e0  = sh + 64*QP16;       // double-buffered entity chunk
    __nv_bfloat16* e1  = e0 + 64*QP16;
    __nv_bfloat16* p_s = e1 + 64*QP16;       // 64 x PPITCH probs

    const int tid = threadIdx.x, warp = tid>>5, lane = tid&31;
    const int start = (int)(((long long)sp     * N) / splits);
    const int end   = (int)(((long long)(sp+1) * N) / splits);
    const int nch   = (end - start + 63) >> 6;

    const unsigned qb = smem_u32(q_s);
    const unsigned ebuf0 = smem_u32(e0);
    const unsigned ebuf1 = smem_u32(e1);
    const unsigned pb = smem_u32(p_s);

    // prologue: async load Q tile + first E chunk (one group), then wait
    for (int i = tid; i < 2048; i += 128) {
        int r = i>>5, c = i&31;
        cpasync16(qb + (r*QP16 + c*8)*2, Q + ((bt*64 + r)<<8) + c*8);
    }
    for (int i = tid; i < 2048; i += 128) {
        int r = i>>5, c = i&31;
        cpasync16(ebuf0 + (r*QP16 + c*8)*2, tbl + ((start + r)<<8) + c*8);
    }
    CP_COMMIT();

    // per-lane address bases
    const int am = lane>>3;
    const unsigned aBase = qb + (((warp<<4) + (lane&7) + ((am&1)<<3))*QP16 + ((am>>1)<<3))*2;
    const unsigned sB4 = ((lane&7)*QP16 + ((lane>>3)&1)*8 + ((lane>>4)*8*QP16))*2;
    // PV: E^T B-frags, warp's 64-col slice
    const unsigned tB4 = ((lane&15)*QP16 + ((lane>>4)<<3) + warp*64)*2;
    // PV: P A-frags (pitch PPITCH), per m-tile base (mt folded in at use)
    const unsigned aPOff = pb + (((lane&7) + ((am&1)<<3))*PPITCH + ((am>>1)<<3))*2;
    // P write: this thread's two row slots
    const unsigned pwA = pb + ((warp*16 + (lane>>2))*PPITCH + (lane&3)*2)*2;
    const unsigned pwB = pwA + 8*PPITCH*2;

    CP_WAIT_0();
    __syncthreads();          // Q + E0 resident

    // hoist Q A-fragments for kt = 0..7 (loop-invariant)
    unsigned aF[8][4];
#pragma unroll
    for (int kt = 0; kt < 8; kt++) ldsm4(aF[kt], aBase + kt*32);

    float o[32][4];           // [mt*8 + ct]: 4 m-tiles x 8 col-tiles (warp's 64-col slice)
#pragma unroll
    for (int i = 0; i < 32; i++) { o[i][0]=0.f; o[i][1]=0.f; o[i][2]=0.f; o[i][3]=0.f; }
    float lA = 0.f, lB = 0.f;

    for (int c = 0; c < nch; c++) {
        const int pos = start + (c<<6);

        // prefetch next chunk (targets buffer read two iters ago — safe past top barrier)
        if (c + 1 < nch) {
            const int p2 = start + ((c+1)<<6);
            const unsigned ed = ((c+1)&1) ? ebuf1 : ebuf0;
            for (int i = tid; i < 2048; i += 128) {
                int r = i>>5, cc = i&31;
                cpasync16(ed + (r*QP16 + cc*8)*2, tbl + ((p2 + r)<<8) + cc*8);
            }
            CP_COMMIT();
        }

        const unsigned e = (c&1) ? ebuf1 : ebuf0;

        // ---- S = Q @ E^T (row-split: this warp's 16 rows x all 64 ents) ----
        float s[8][4];
#pragma unroll
        for (int i = 0; i < 8; i++) { s[i][0]=0.f; s[i][1]=0.f; s[i][2]=0.f; s[i][3]=0.f; }
#pragma unroll
        for (int kt = 0; kt < 16; kt++) {
            unsigned a[4];
            if (kt < 8) { a[0]=aF[kt][0]; a[1]=aF[kt][1]; a[2]=aF[kt][2]; a[3]=aF[kt][3]; }
            else        ldsm4(a, aBase + kt*32);
#pragma unroll
            for (int nt = 0; nt < 8; nt += 2) {
                unsigned r[4];
                ldsm4(r, e + sB4 + (nt*8*QP16)*2 + kt*32);
                mma16816(s[nt],   a, r[0], r[1]);
                mma16816(s[nt+1], a, r[2], r[3]);
            }
        }

        // ---- P = exp(S); mask ragged tail; write P tile to smem ----
        if (pos + 64 <= end) {
#pragma unroll
            for (int nt = 0; nt < 8; nt++) {
                s[nt][0] = __expf(s[nt][0]);
                s[nt][1] = __expf(s[nt][1]);
                s[nt][2] = __expf(s[nt][2]);
                s[nt][3] = __expf(s[nt][3]);
                lA += s[nt][0] + s[nt][1];
                lB += s[nt][2] + s[nt][3];
            }
        } else {
            const int cb = pos + ((lane&3)<<1);
#pragma unroll
            for (int nt = 0; nt < 8; nt++) {
                int c0 = cb + (nt<<3);
                s[nt][0] = (c0   < end) ? __expf(s[nt][0]) : 0.f;
                s[nt][1] = (c0+1 < end) ? __expf(s[nt][1]) : 0.f;
                s[nt][2] = (c0   < end) ? __expf(s[nt][2]) : 0.f;
                s[nt][3] = (c0+1 < end) ? __expf(s[nt][3]) : 0.f;
                lA += s[nt][0] + s[nt][1];
                lB += s[nt][2] + s[nt][3];
            }
        }
#pragma unroll
        for (int nt = 0; nt < 8; nt++) {
            unsigned vA = packbf(s[nt][0], s[nt][1]);
            unsigned vB = packbf(s[nt][2], s[nt][3]);
            asm volatile("st.shared.b32 [%0], %1;" :: "r"(pwA + nt*16), "r"(vA) : "memory");
            asm volatile("st.shared.b32 [%0], %1;" :: "r"(pwB + nt*16), "r"(vB) : "memory");
        }
        __syncthreads();      // P tile complete, all warps

        // ---- O += P @ E (col-split: all 64 rows x this warp's 64 cols) ----
#pragma unroll
        for (int k2 = 0; k2 < 4; k2++) {
            unsigned Bc[4][4];
#pragma unroll
            for (int j = 0; j < 4; j++)
                ldsm4t(Bc[j], e + tB4 + ((k2*16*QP16) + (j<<4))*2);
#pragma unroll
            for (int mt = 0; mt < 4; mt++) {
                unsigned a[4];
                ldsm4(a, aPOff + (mt*16*PPITCH + k2*16)*2);
#pragma unroll
                for (int j = 0; j < 4; j++) {
                    mma16816(o[mt*8 + 2*j],     a, Bc[j][0], Bc[j][1]);
                    mma16816(o[mt*8 + 2*j + 1], a, Bc[j][2], Bc[j][3]);
                }
            }
        }

        // end-of-chunk barrier: next E data ready + P/E buffers free for reuse
        if (c + 1 < nch) {
            CP_WAIT_0();
            __syncthreads();
        }
    }

    // ---- epilogue: write O partial (col-split layout) + row-sum partial ----
    float* pa = pacc + (size_t)sp*NB*EMB;
#pragma unroll
    for (int mt = 0; mt < 4; mt++) {
        int rA2 = (bt<<6) + mt*16 + (lane>>2);
        int rB2 = rA2 + 8;
#pragma unroll
        for (int ct = 0; ct < 8; ct++) {
            int col = warp*64 + ct*8 + ((lane&3)<<1);
            *(float2*)(pa + rA2*EMB + col) = make_float2(o[mt*8+ct][0], o[mt*8+ct][1]);
            *(float2*)(pa + rB2*EMB + col) = make_float2(o[mt*8+ct][2], o[mt*8+ct][3]);
        }
    }
    lA += __shfl_xor_sync(0xffffffff, lA, 1);
    lA += __shfl_xor_sync(0xffffffff, lA, 2);
    lB += __shfl_xor_sync(0xffffffff, lB, 1);
    lB += __shfl_xor_sync(0xffffffff, lB, 2);
    if ((lane&3) == 0) {
        int rA = (bt<<6) + (warp<<4) + (lane>>2);
        pl[sp*NB + rA] = lA;
        pl[sp*NB + rA + 8] = lB;
    }
}

// ---------------- finish: combine all three attends + passthrough copies -------------
// grid 1024 x 128: block handles half a row (128 cols).
__global__ __launch_bounds__(128) void finish_kernel(
    const float* __restrict__ left_child,
    const float* __restrict__ right_child,
    float* __restrict__ out)
{
    const int b = blockIdx.x >> 1;
    const int c = ((blockIdx.x & 1) << 7) + threadIdx.x;

    // ent -> new_left[:,2,:] and new_right[:,0,:]
    {
        float L = 0.f, a = 0.f;
        for (int s = 0; s < SPLITS_E; s++) {
            L += g_pl0[s*NB + b];
            a += g_pacc0[((size_t)s*NB + b)*EMB + c];
        }
        float o = a / L;
        out[512 + b*768 + c] = o;
        out[393216 + b*768 + c] = o;
    }
    // left rel -> new_left[:,1,:]
    {
        float L = 0.f, a = 0.f;
        for (int s = 0; s < SPLITS_R; s++) {
            L += g_pl1[s*NB + b];
            a += g_pacc1[((size_t)s*NB + b)*EMB + c];
        }
        out[256 + b*768 + c] = a / L;
    }
    // right rel -> new_right[:,1,:]
    {
        float L = 0.f, a = 0.f;
        for (int s = 0; s < SPLITS_R; s++) {
            L += g_pl2[s*NB + b];
            a += g_pacc2[((size_t)s*NB + b)*EMB + c];
        }
        out[393216 + 256 + b*768 + c] = a / L;
    }
    // passthrough
    out[b*768 + c] = left_child[b*768 + c];
    out[393216 + b*768 + 512 + c] = right_child[b*768 + 512 + c];
}

extern "C" void kernel_launch(void* const* d_in, const int* in_sizes, int n_in,
                              void* d_out, int out_size)
{
    const float* left_child  = (const float*)d_in[0];
    const float* right_child = (const float*)d_in[1];
    const float* query       = (const float*)d_in[2];
    const float* ent_emb     = (const float*)d_in[3];
    const float* rel_emb     = (const float*)d_in[4];
    const float* W_left      = (const float*)d_in[5];
    const float* b_left      = (const float*)d_in[6];
    const float* W_right     = (const float*)d_in[7];
    const float* b_right     = (const float*)d_in[8];
    const float* W_ent       = (const float*)d_in[9];
    const float* b_ent       = (const float*)d_in[10];
    float* out = (float*)d_out;

    cudaFuncSetAttribute(flash16,
                         cudaFuncAttributeMaxDynamicSharedMemorySize, FL_SMEM);

    conv_all<<<13118, 256>>>(ent_emb, rel_emb, query, W_left, W_right, W_ent);
    proj16<<<dim3(8, 12), 128>>>(b_left, b_right, b_ent);
    flash16<<<424, 128, FL_SMEM>>>(0);
    finish_kernel<<<1024, 128>>>(left_child, right_child, out);
}

// round 14
// speedup vs baseline: 1.0369x; 1.0369x over previous
#include <cuda_runtime.h>
#include <cuda_bf16.h>
#include <cstdint>
#include <cstddef>
#include <math.h>

#define EMB   256
#define NB    512
#define ENT_N 100000
#define REL_N 2000
#define SPLITS_E 37
#define SPLITS_R 8
#define QP16  264                 // bf16 pitch for 256-wide tiles (+8 pad, 16B aligned)
#define FL_SMEM (3*64*QP16*2)     // Q tile + 2 E buffers = 101376 B

// ---------------- scratch (device globals; no allocation) ----------------
__device__ __align__(16) __nv_bfloat16 g_qe16[NB*EMB];
__device__ __align__(16) __nv_bfloat16 g_ql16[NB*EMB];
__device__ __align__(16) __nv_bfloat16 g_qr16[NB*EMB];
__device__ __align__(16) __nv_bfloat16 g_ent16[(ENT_N+64)*EMB];
__device__ __align__(16) __nv_bfloat16 g_rel16[(REL_N+64)*EMB];
__device__ __align__(16) __nv_bfloat16 g_q16[NB*768];      // bf16 q_cat
__device__ __align__(16) __nv_bfloat16 g_wl16[256*256];
__device__ __align__(16) __nv_bfloat16 g_wr16[256*256];
__device__ __align__(16) __nv_bfloat16 g_we16[256*768];

__device__ __align__(16) __nv_bfloat16 g_pacc0[SPLITS_E*NB*EMB];
__device__ float g_pl0[SPLITS_E*NB];
__device__ __align__(16) __nv_bfloat16 g_pacc1[SPLITS_R*NB*EMB];
__device__ float g_pl1[SPLITS_R*NB];
__device__ __align__(16) __nv_bfloat16 g_pacc2[SPLITS_R*NB*EMB];
__device__ float g_pl2[SPLITS_R*NB];

// ---------------- small PTX helpers ----------------
__device__ __forceinline__ unsigned smem_u32(const void* p){
    return (unsigned)__cvta_generic_to_shared(p);
}
__device__ __forceinline__ void ldsm4(unsigned* r, unsigned addr){
    asm volatile("ldmatrix.sync.aligned.m8n8.x4.shared.b16 {%0,%1,%2,%3}, [%4];"
      : "=r"(r[0]),"=r"(r[1]),"=r"(r[2]),"=r"(r[3]) : "r"(addr));
}
__device__ __forceinline__ void ldsm4t(unsigned* r, unsigned addr){
    asm volatile("ldmatrix.sync.aligned.m8n8.x4.trans.shared.b16 {%0,%1,%2,%3}, [%4];"
      : "=r"(r[0]),"=r"(r[1]),"=r"(r[2]),"=r"(r[3]) : "r"(addr));
}
__device__ __forceinline__ void mma16816(float* d, const unsigned* a, unsigned b0, unsigned b1){
    asm volatile("mma.sync.aligned.m16n8k16.row.col.f32.bf16.bf16.f32 "
      "{%0,%1,%2,%3}, {%4,%5,%6,%7}, {%8,%9}, {%0,%1,%2,%3};"
      : "+f"(d[0]),"+f"(d[1]),"+f"(d[2]),"+f"(d[3])
      : "r"(a[0]),"r"(a[1]),"r"(a[2]),"r"(a[3]), "r"(b0),"r"(b1));
}
__device__ __forceinline__ void cpasync16(unsigned dst, const void* src){
    asm volatile("cp.async.cg.shared.global [%0], [%1], 16;" :: "r"(dst), "l"(src));
}
#define CP_COMMIT() asm volatile("cp.async.commit_group;" ::: "memory")
#define CP_WAIT_1() asm volatile("cp.async.wait_group 1;" ::: "memory")
#define CP_WAIT_0() asm volatile("cp.async.wait_group 0;" ::: "memory")

__device__ __forceinline__ unsigned packbf(float lo, float hi){
    __nv_bfloat162 h = __floats2bfloat162_rn(lo, hi);
    return *reinterpret_cast<unsigned*>(&h);
}

// ---------------- merged fp32 -> bf16 conversions (8 elems/thread) ----------------
// segments: ent(pad) | rel(pad) | query | Wl | Wr | We   (all boundaries 8-divisible)
#define S0E 25616384LL
#define S1E 26144768LL
#define S2E 26537984LL
#define S3E 26603520LL
#define S4E 26669056LL
#define S5E 26865664LL
__global__ __launch_bounds__(256) void conv_all(
    const float* __restrict__ ent, const float* __restrict__ rel,
    const float* __restrict__ query,
    const float* __restrict__ Wl, const float* __restrict__ Wr,
    const float* __restrict__ We)
{
    long long i = ((long long)blockIdx.x*256 + threadIdx.x)*8;
    if (i >= S5E) return;
    const float* src; __nv_bfloat16* dst; long long off, n;
    if (i < S0E)      { src=ent;   dst=g_ent16; off=i;       n=25600000LL; }
    else if (i < S1E) { src=rel;   dst=g_rel16; off=i-S0E;   n=512000LL; }
    else if (i < S2E) { src=query; dst=g_q16;   off=i-S1E;   n=393216LL; }
    else if (i < S3E) { src=Wl;    dst=g_wl16;  off=i-S2E;   n=65536LL; }
    else if (i < S4E) { src=Wr;    dst=g_wr16;  off=i-S3E;   n=65536LL; }
    else              { src=We;    dst=g_we16;  off=i-S4E;   n=196608LL; }
    float4 v0 = make_float4(0.f,0.f,0.f,0.f), v1 = v0;
    if (off < n) {
        v0 = *(const float4*)(src+off);
        v1 = *(const float4*)(src+off+4);
    }
    uint4 o;
    o.x = packbf(v0.x, v0.y);
    o.y = packbf(v0.z, v0.w);
    o.z = packbf(v1.x, v1.y);
    o.w = packbf(v1.z, v1.w);
    *(uint4*)(dst+off) = o;
}

// ---------------- projections via bf16 mma: q_ent / left_rel / right_rel ----------
// grid (8 bt, 12 nc): nc>>2 = mat (0=L,1=R,2=E), (nc&3)*64 = output col chunk.
#define PJP 72   // smem pitch (64+8)
__global__ __launch_bounds__(128) void proj16(
    const float* __restrict__ bl, const float* __restrict__ br,
    const float* __restrict__ be)
{
    __shared__ __nv_bfloat16 ts[4][64*PJP];   // q0,q1,w0,w1

    const int bt = blockIdx.x, nc = blockIdx.y;
    const int mat = nc >> 2, ncol = (nc & 3) * 64;
    const __nv_bfloat16 *W, *Qb;
    const float* bias;
    __nv_bfloat16* dst;
    int K;
    if (mat == 0)      { W = g_wl16 + ncol*256; bias = bl; dst = g_ql16; K = 256; Qb = g_q16 + 256; }
    else if (mat == 1) { W = g_wr16 + ncol*256; bias = br; dst = g_qr16; K = 256; Qb = g_q16 + 256; }
    else               { W = g_we16 + ncol*768; bias = be; dst = g_qe16; K = 768; Qb = g_q16; }
    const int nk = K >> 6;

    const int tid = threadIdx.x, warp = tid>>5, lane = tid&31;
    const unsigned qs[2] = { smem_u32(ts[0]), smem_u32(ts[1]) };
    const unsigned ws[2] = { smem_u32(ts[2]), smem_u32(ts[3]) };

    const int lr = tid >> 3, lc8 = (tid & 7) * 8;
    {
#pragma unroll
        for (int j = 0; j < 4; j++) {
            int r = lr + j*16;
            cpasync16(qs[0] + (r*PJP + lc8)*2, Qb + (bt*64 + r)*768 + lc8);
            cpasync16(ws[0] + (r*PJP + lc8)*2, W + r*K + lc8);
        }
        CP_COMMIT();
    }

    const int am = lane>>3;
    const unsigned aOff = (((warp<<4) + (lane&7) + ((am&1)<<3))*PJP + ((am>>1)<<3))*2;
    const unsigned bOff = ((lane&7)*PJP + ((lane>>3)&1)*8 + ((lane>>4)*8*PJP))*2;

    float s[8][4];
#pragma unroll
    for (int i = 0; i < 8; i++) { s[i][0]=0.f; s[i][1]=0.f; s[i][2]=0.f; s[i][3]=0.f; }

    for (int kc = 0; kc < nk; kc++) {
        if (kc + 1 < nk) {
            const int koff = (kc+1)*64;
            const unsigned qd = qs[(kc+1)&1], wd = ws[(kc+1)&1];
#pragma unroll
            for (int j = 0; j < 4; j++) {
                int r = lr + j*16;
                cpasync16(qd + (r*PJP + lc8)*2, Qb + (bt*64 + r)*768 + koff + lc8);
                cpasync16(wd + (r*PJP + lc8)*2, W + r*K + koff + lc8);
            }
            CP_COMMIT();
            CP_WAIT_1();
        } else {
            CP_WAIT_0();
        }
        __syncthreads();
        const unsigned qb = qs[kc&1], wb = ws[kc&1];
#pragma unroll
        for (int kt = 0; kt < 4; kt++) {
            unsigned a[4]; ldsm4(a, qb + aOff + kt*32);
#pragma unroll
            for (int nt = 0; nt < 8; nt += 2) {
                unsigned r[4];
                ldsm4(r, wb + bOff + (nt*8*PJP)*2 + kt*32);
                mma16816(s[nt],   a, r[0], r[1]);
                mma16816(s[nt+1], a, r[2], r[3]);
            }
        }
        __syncthreads();
    }

    const int rowA = bt*64 + warp*16 + (lane>>2);
    const int rowB = rowA + 8;
#pragma unroll
    for (int nt = 0; nt < 8; nt++) {
        int col = ncol + nt*8 + (lane&3)*2;
        float b0 = bias[col], b1 = bias[col+1];
        *(__nv_bfloat162*)(dst + rowA*EMB + col) = __floats2bfloat162_rn(s[nt][0]+b0, s[nt][1]+b1);
        *(__nv_bfloat162*)(dst + rowB*EMB + col) = __floats2bfloat162_rn(s[nt][2]+b0, s[nt][3]+b1);
    }
}

// ---------------- bf16 tensor-core flash attend (merged ent+rel, split-K) -----------
// 424 blocks: [0,296) ent, [296,360) left rel, [360,424) right rel.  (M=64, 2 blk/SM)
// Q A-fragments (kt<8) hoisted to registers; single barrier per chunk; bf16 partials.
__global__ __launch_bounds__(128) void flash16(int dummy)
{
    int id = blockIdx.x;
    const __nv_bfloat16 *Q, *tbl;
    __nv_bfloat16 *pacc;
    float *pl;
    int N, splits;
    if (id < 296)      { Q = g_qe16; tbl = g_ent16; pacc = g_pacc0; pl = g_pl0; N = ENT_N; splits = SPLITS_E; }
    else if (id < 360) { id -= 296; Q = g_ql16; tbl = g_rel16; pacc = g_pacc1; pl = g_pl1; N = REL_N; splits = SPLITS_R; }
    else               { id -= 360; Q = g_qr16; tbl = g_rel16; pacc = g_pacc2; pl = g_pl2; N = REL_N; splits = SPLITS_R; }
    const int bt = id & 7, sp = id >> 3;

    extern __shared__ __nv_bfloat16 sh[];
    __nv_bfloat16* q_s = sh;                 // 64 x QP16
    __nv_bfloat16* e0  = sh + 64*QP16;       // double-buffered entity chunk
    __nv_bfloat16* e1  = e0 + 64*QP16;

    const int tid = threadIdx.x, warp = tid>>5, lane = tid&31;
    const int start = (int)(((long long)sp     * N) / splits);
    const int end   = (int)(((long long)(sp+1) * N) / splits);
    const int nch   = (end - start + 63) >> 6;

    const unsigned qb = smem_u32(q_s);
    const unsigned ebuf0 = smem_u32(e0);
    const unsigned ebuf1 = smem_u32(e1);

    // prologue: async load Q tile + first E chunk (one group), then wait
    for (int i = tid; i < 2048; i += 128) {
        int r = i>>5, c = i&31;
        cpasync16(qb + (r*QP16 + c*8)*2, Q + ((bt*64 + r)<<8) + c*8);
    }
    for (int i = tid; i < 2048; i += 128) {
        int r = i>>5, c = i&31;
        cpasync16(ebuf0 + (r*QP16 + c*8)*2, tbl + ((start + r)<<8) + c*8);
    }
    CP_COMMIT();

    // per-lane ldmatrix address bases
    const int am = lane>>3;
    const unsigned aBase = qb + (((warp<<4) + (lane&7) + ((am&1)<<3))*QP16 + ((am>>1)<<3))*2;
    const unsigned sB4 = ((lane&7)*QP16 + ((lane>>3)&1)*8 + ((lane>>4)*8*QP16))*2;
    const unsigned tB4 = ((lane&15)*QP16 + ((lane>>4)<<3))*2;

    CP_WAIT_0();
    __syncthreads();          // Q + E0 resident

    // hoist Q A-fragments for kt = 0..7 (loop-invariant)
    unsigned aF[8][4];
#pragma unroll
    for (int kt = 0; kt < 8; kt++) ldsm4(aF[kt], aBase + kt*32);

    float o[32][4];
#pragma unroll
    for (int i = 0; i < 32; i++) { o[i][0]=0.f; o[i][1]=0.f; o[i][2]=0.f; o[i][3]=0.f; }
    float lA = 0.f, lB = 0.f;

    for (int c = 0; c < nch; c++) {
        const int pos = start + (c<<6);

        // prefetch next chunk (targets buffer read two iters ago — safe past top barrier)
        if (c + 1 < nch) {
            const int p2 = start + ((c+1)<<6);
            const unsigned ed = ((c+1)&1) ? ebuf1 : ebuf0;
            for (int i = tid; i < 2048; i += 128) {
                int r = i>>5, cc = i&31;
                cpasync16(ed + (r*QP16 + cc*8)*2, tbl + ((p2 + r)<<8) + cc*8);
            }
            CP_COMMIT();
        }

        const unsigned e = (c&1) ? ebuf1 : ebuf0;

        // ---- S = Q @ E^T (16 k-steps x 4 n-tile-pairs via ldsm4) ----
        float s[8][4];
#pragma unroll
        for (int i = 0; i < 8; i++) { s[i][0]=0.f; s[i][1]=0.f; s[i][2]=0.f; s[i][3]=0.f; }
#pragma unroll
        for (int kt = 0; kt < 16; kt++) {
            unsigned a[4];
            if (kt < 8) { a[0]=aF[kt][0]; a[1]=aF[kt][1]; a[2]=aF[kt][2]; a[3]=aF[kt][3]; }
            else        ldsm4(a, aBase + kt*32);
#pragma unroll
            for (int nt = 0; nt < 8; nt += 2) {
                unsigned r[4];
                ldsm4(r, e + sB4 + (nt*8*QP16)*2 + kt*32);
                mma16816(s[nt],   a, r[0], r[1]);
                mma16816(s[nt+1], a, r[2], r[3]);
            }
        }

        // ---- P = exp(S) (|S| small, no max); mask only ragged tail chunks ----
        if (pos + 64 <= end) {
#pragma unroll
            for (int nt = 0; nt < 8; nt++) {
                s[nt][0] = __expf(s[nt][0]);
                s[nt][1] = __expf(s[nt][1]);
                s[nt][2] = __expf(s[nt][2]);
                s[nt][3] = __expf(s[nt][3]);
                lA += s[nt][0] + s[nt][1];
                lB += s[nt][2] + s[nt][3];
            }
        } else {
            const int cb = pos + ((lane&3)<<1);
#pragma unroll
            for (int nt = 0; nt < 8; nt++) {
                int c0 = cb + (nt<<3);
                s[nt][0] = (c0   < end) ? __expf(s[nt][0]) : 0.f;
                s[nt][1] = (c0+1 < end) ? __expf(s[nt][1]) : 0.f;
                s[nt][2] = (c0   < end) ? __expf(s[nt][2]) : 0.f;
                s[nt][3] = (c0+1 < end) ? __expf(s[nt][3]) : 0.f;
                lA += s[nt][0] + s[nt][1];
                lB += s[nt][2] + s[nt][3];
            }
        }

        // ---- O += P @ E (P register-resident; E^T frags via ldsm4 trans) ----
#pragma unroll
        for (int k2 = 0; k2 < 4; k2++) {
            unsigned a[4];
            a[0] = packbf(s[2*k2  ][0], s[2*k2  ][1]);
            a[1] = packbf(s[2*k2  ][2], s[2*k2  ][3]);
            a[2] = packbf(s[2*k2+1][0], s[2*k2+1][1]);
            a[3] = packbf(s[2*k2+1][2], s[2*k2+1][3]);
#pragma unroll
            for (int nt2 = 0; nt2 < 32; nt2 += 2) {
                unsigned r[4];
                ldsm4t(r, e + tB4 + ((k2*16*QP16) + (nt2<<3))*2);
                mma16816(o[nt2],   a, r[0], r[1]);
                mma16816(o[nt2+1], a, r[2], r[3]);
            }
        }

        // single barrier per chunk: next data ready + all warps done with this buffer
        if (c + 1 < nch) {
            CP_WAIT_0();
            __syncthreads();
        }
    }

    // ---- epilogue: write O partial (bf16 pairs) + row-sum partial ----
    const int rA = (bt<<6) + (warp<<4) + (lane>>2);
    const int rB = rA + 8;
    __nv_bfloat16* pa = pacc + (size_t)sp*NB*EMB;
#pragma unroll
    for (int nt2 = 0; nt2 < 32; nt2++) {
        int col = (nt2<<3) + ((lane&3)<<1);
        *(__nv_bfloat162*)(pa + rA*EMB + col) = __floats2bfloat162_rn(o[nt2][0], o[nt2][1]);
        *(__nv_bfloat162*)(pa + rB*EMB + col) = __floats2bfloat162_rn(o[nt2][2], o[nt2][3]);
    }
    lA += __shfl_xor_sync(0xffffffff, lA, 1);
    lA += __shfl_xor_sync(0xffffffff, lA, 2);
    lB += __shfl_xor_sync(0xffffffff, lB, 1);
    lB += __shfl_xor_sync(0xffffffff, lB, 2);
    if ((lane&3) == 0) {
        pl[sp*NB + rA] = lA;
        pl[sp*NB + rB] = lB;
    }
}

// ---------------- finish: combine bf16 partials + passthrough copies -------------
// grid 512 x 128: block = one batch row, thread = column pair (bf16x2 loads).
__global__ __launch_bounds__(128) void finish_kernel(
    const float* __restrict__ left_child,
    const float* __restrict__ right_child,
    float* __restrict__ out)
{
    const int b = blockIdx.x;
    const int c2 = threadIdx.x * 2;

    // ent -> new_left[:,2,:] and new_right[:,0,:]
    {
        float L = 0.f, a0 = 0.f, a1 = 0.f;
        for (int s = 0; s < SPLITS_E; s++) {
            L += g_pl0[s*NB + b];
            __nv_bfloat162 v = *(const __nv_bfloat162*)(g_pacc0 + ((size_t)s*NB + b)*EMB + c2);
            a0 += __bfloat162float(v.x);
            a1 += __bfloat162float(v.y);
        }
        float2 o2 = make_float2(a0 / L, a1 / L);
        *(float2*)(out + 512 + b*768 + c2) = o2;
        *(float2*)(out + 393216 + b*768 + c2) = o2;
    }
    // left rel -> new_left[:,1,:]
    {
        float L = 0.f, a0 = 0.f, a1 = 0.f;
        for (int s = 0; s < SPLITS_R; s++) {
            L += g_pl1[s*NB + b];
            __nv_bfloat162 v = *(const __nv_bfloat162*)(g_pacc1 + ((size_t)s*NB + b)*EMB + c2);
            a0 += __bfloat162float(v.x);
            a1 += __bfloat162float(v.y);
        }
        *(float2*)(out + 256 + b*768 + c2) = make_float2(a0 / L, a1 / L);
    }
    // right rel -> new_right[:,1,:]
    {
        float L = 0.f, a0 = 0.f, a1 = 0.f;
        for (int s = 0; s < SPLITS_R; s++) {
            L += g_pl2[s*NB + b];
            __nv_bfloat162 v = *(const __nv_bfloat162*)(g_pacc2 + ((size_t)s*NB + b)*EMB + c2);
            a0 += __bfloat162float(v.x);
            a1 += __bfloat162float(v.y);
        }
        *(float2*)(out + 393216 + 256 + b*768 + c2) = make_float2(a0 / L, a1 / L);
    }
    // passthrough (fp32 pairs)
    *(float2*)(out + b*768 + c2) = *(const float2*)(left_child + b*768 + c2);
    *(float2*)(out + 393216 + b*768 + 512 + c2) = *(const float2*)(right_child + b*768 + 512 + c2);
}

extern "C" void kernel_launch(void* const* d_in, const int* in_sizes, int n_in,
                              void* d_out, int out_size)
{
    const float* left_child  = (const float*)d_in[0];
    const float* right_child = (const float*)d_in[1];
    const float* query       = (const float*)d_in[2];
    const float* ent_emb     = (const float*)d_in[3];
    const float* rel_emb     = (const float*)d_in[4];
    const float* W_left      = (const float*)d_in[5];
    const float* b_left      = (const float*)d_in[6];
    const float* W_right     = (const float*)d_in[7];
    const float* b_right     = (const float*)d_in[8];
    const float* W_ent       = (const float*)d_in[9];
    const float* b_ent       = (const float*)d_in[10];
    float* out = (float*)d_out;

    cudaFuncSetAttribute(flash16,
                         cudaFuncAttributeMaxDynamicSharedMemorySize, FL_SMEM);

    conv_all<<<13118, 256>>>(ent_emb, rel_emb, query, W_left, W_right, W_ent);
    proj16<<<dim3(8, 12), 128>>>(b_left, b_right, b_ent);
    flash16<<<424, 128, FL_SMEM>>>(0);
    finish_kernel<<<NB, 128>>>(left_child, right_child, out);
}